// round 12
// baseline (speedup 1.0000x reference)
#include <cuda_runtime.h>
#include <cuda_fp16.h>
#include <cstdint>

#define NT 256
#define LN_EPS 1e-5f
#define MAX_NODES 100000

// smem byte offsets
#define SB_W1  0          // __half W1 packed: 64 cols x stride 80 halves  = 10240 B
#define SB_WB  10240      // __half Wbig packed: 72 cols x stride 208 halves = 29952 B
#define SB_BI  40192      // float b_init [64]
#define SB_BMX 40448      // float folded bias [65]+pad
#define SMEM_BYTES 40720

__device__ int    g_edges_is_i64;
__device__ __half g_w1[64 * 80];
__device__ __half g_wb[72 * 208];
__device__ float  g_bi[64];
__device__ float  g_bmx[68];
__device__ __half g_nodeh[MAX_NODES * 64];   // 12.8 MB fp16 node cache

// N-permutation: logical frag col -> actual col (thread's 16 cols = 4 float4s)
__device__ __host__ __forceinline__ int sigp(int c) {
    return 16 * (c >> 4) + 4 * ((c & 7) >> 1) + 2 * ((c >> 3) & 1) + (c & 1);
}

__global__ void prep_all(const float* __restrict__ W_init,
                         const float* __restrict__ b_init,
                         const float* __restrict__ W_mlp,
                         const float* __restrict__ b_mlp,
                         const float* __restrict__ W_alpha,
                         const float* __restrict__ b_alpha,
                         const long long* __restrict__ e64)
{
    int i = blockIdx.x * blockDim.x + threadIdx.x;
    if (i == 0) {
        int ok = 1;
        for (int j = 0; j < 64; ++j) {
            long long v = e64[j];
            if (v < 0 || v >= (1LL << 31)) ok = 0;
        }
        g_edges_is_i64 = ok;
    }
    if (i < 64 * 64) {
        int c = i >> 6, k = i & 63;
        g_w1[c * 80 + k] = __float2half_rn(W_init[sigp(c) * 64 + k]);
    } else if (i < 64 * 64 + 72 * 192) {
        int j = i - 64 * 64;
        int c = j / 192, k = j - c * 192;
        float v = 0.f;
        if (c < 64) {
            int a = sigp(c);
            if (k < 64) {
                float s = 0.f;
                #pragma unroll 8
                for (int m = 0; m < 64; ++m) s += W_mlp[a * 192 + m] * W_init[m * 64 + k];
                v = s;
            } else v = W_mlp[a * 192 + k];
        } else if (c == 64) {
            if (k < 64) {
                float s = 0.f;
                #pragma unroll 8
                for (int m = 0; m < 64; ++m) s += W_alpha[m] * W_init[m * 64 + k];
                v = s;
            } else v = W_alpha[k];
        }
        g_wb[c * 208 + k] = __float2half_rn(v);
    } else if (i < 64 * 64 + 72 * 192 + 64) {
        int t = i - (64 * 64 + 72 * 192);
        g_bi[t] = b_init[t];
    } else if (i < 64 * 64 + 72 * 192 + 64 + 65) {
        int t = i - (64 * 64 + 72 * 192 + 64);
        float s = (t < 64) ? b_mlp[t] : b_alpha[0];
        const float* wr = (t < 64) ? (W_mlp + t * 192) : W_alpha;
        #pragma unroll 8
        for (int m = 0; m < 64; ++m) s += b_init[m] * wr[m];
        g_bmx[t] = s;
    }
}

// convert node features to fp16 (rn) — identical values to in-kernel conversion
__global__ void prep_node(const float* __restrict__ node_fts, int n4)
{
    int i = blockIdx.x * blockDim.x + threadIdx.x;
    if (i < n4) {
        float4 v = __ldg((const float4*)node_fts + i);
        __half2 h0 = __floats2half2_rn(v.x, v.y);
        __half2 h1 = __floats2half2_rn(v.z, v.w);
        uint2 u = { *(uint32_t*)&h0, *(uint32_t*)&h1 };
        *((uint2*)g_nodeh + i) = u;
    }
}

__device__ __forceinline__ uint32_t H2(float a, float b) {
    __half2 h = __floats2half2_rn(a, b);
    return *(uint32_t*)&h;
}
__device__ __forceinline__ void mma_f16(float c[4], uint32_t a0, uint32_t a1, uint32_t a2,
                                        uint32_t a3, uint32_t b0, uint32_t b1) {
    asm volatile(
        "mma.sync.aligned.m16n8k16.row.col.f32.f16.f16.f32 "
        "{%0,%1,%2,%3}, {%4,%5,%6,%7}, {%8,%9}, {%0,%1,%2,%3};\n"
        : "+f"(c[0]), "+f"(c[1]), "+f"(c[2]), "+f"(c[3])
        : "r"(a0), "r"(a1), "r"(a2), "r"(a3), "r"(b0), "r"(b1));
}

__global__ void __launch_bounds__(NT, 2)
edge_update_v11(const float* __restrict__ edge_fts,
                const void* __restrict__ edges_raw,
                float* __restrict__ out,
                int n_edges)
{
    extern __shared__ char smc[];
    const int tid = threadIdx.x;
    {
        int4* d = (int4*)smc;
        const int4* s1 = (const int4*)g_w1;
        for (int i = tid; i < 10240 / 16; i += NT) d[i] = s1[i];
        int4* d2 = (int4*)(smc + SB_WB);
        const int4* s2 = (const int4*)g_wb;
        for (int i = tid; i < 29952 / 16; i += NT) d2[i] = s2[i];
        float* bf = (float*)(smc + SB_BI);
        if (tid < 64) bf[tid] = g_bi[tid];
        float* bm = (float*)(smc + SB_BMX);
        if (tid < 65) bm[tid] = g_bmx[tid];
    }
    __syncthreads();

    const __half* sw1 = (const __half*)(smc + SB_W1);
    const __half* swb = (const __half*)(smc + SB_WB);
    const float*  sbi = (const float*)(smc + SB_BI);
    const float*  sbm = (const float*)(smc + SB_BMX);

    const int wid  = tid >> 5;
    const int lane = tid & 31;
    const int gq   = lane >> 2;
    const int t4   = lane & 3;
    const int is64 = g_edges_is_i64;
    const long long* e64 = (const long long*)edges_raw;
    const int*       e32 = (const int*)edges_raw;
    const float bma = sbm[64];

    const char* eB = (const char*)edge_fts;
    const char* nH = (const char*)g_nodeh;
    const int ntiles = (n_edges + 15) >> 4;

    for (int wt = blockIdx.x * 8 + wid; wt < ntiles; wt += gridDim.x * 8) {
        const int tb  = wt << 4;
        const int rem = min(16, n_edges - tb);

        int hidx = 0, tidx = 0;
        if (lane < 16) {
            size_t ep = (size_t)min(tb + lane, n_edges - 1);
            if (is64) { hidx = (int)e64[ep]; tidx = (int)e64[ep + (size_t)n_edges]; }
            else      { hidx = e32[ep];      tidx = e32[ep + (size_t)n_edges]; }
        }
        // edge offsets (fp32, 256B rows) and node offsets (fp16, 128B rows)
        const char* pE[2];
        uint32_t oN[2][2];                     // [head/tail][row-chunk]
        #pragma unroll
        for (int r = 0; r < 2; ++r) {
            const int row = r * 8 + gq;
            const int er  = min(tb + row, n_edges - 1);
            pE[r] = eB + (size_t)er * 256 + (size_t)(t4 * 16);
            const int hi = __shfl_sync(0xffffffffu, hidx, row);
            const int ti = __shfl_sync(0xffffffffu, tidx, row);
            oN[0][r] = (uint32_t)hi * 128u + (uint32_t)(t4 * 8);
            oN[1][r] = (uint32_t)ti * 128u + (uint32_t)(t4 * 8);
        }

        float accE[8][4], accB[9][4];
        #pragma unroll
        for (int b = 0; b < 8; ++b)
            #pragma unroll
            for (int c = 0; c < 4; ++c) accE[b][c] = 0.f;
        #pragma unroll
        for (int b = 0; b < 9; ++b)
            #pragma unroll
            for (int c = 0; c < 4; ++c) accB[b][c] = 0.f;

        // -------- edge phase: s = 0..3 (fp32 load + cvt), both GEMMs --------
        float4 vc0 = __ldg((const float4*)pE[0]);
        float4 vc1 = __ldg((const float4*)pE[1]);
        uint2 nc0, nc1;                        // first node step preload
        #pragma unroll
        for (int s = 0; s < 4; ++s) {
            float4 vn0, vn1;
            if (s < 3) {
                vn0 = __ldg((const float4*)(pE[0] + (s + 1) * 64));
                vn1 = __ldg((const float4*)(pE[1] + (s + 1) * 64));
            } else {
                nc0 = __ldg((const uint2*)(nH + oN[0][0]));
                nc1 = __ldg((const uint2*)(nH + oN[0][1]));
            }
            const uint32_t a0 = H2(vc0.x, vc0.y), a1 = H2(vc1.x, vc1.y);
            const uint32_t a2 = H2(vc0.z, vc0.w), a3 = H2(vc1.z, vc1.w);
            const int ko = s * 16 + 4 * t4;
            #pragma unroll
            for (int nt = 0; nt < 9; ++nt) {
                uint2 w = *(const uint2*)&swb[(nt * 8 + gq) * 208 + ko];
                mma_f16(accB[nt], a0, a1, a2, a3, w.x, w.y);
            }
            #pragma unroll
            for (int nt = 0; nt < 8; ++nt) {
                uint2 w = *(const uint2*)&sw1[(nt * 8 + gq) * 80 + ko];
                mma_f16(accE[nt], a0, a1, a2, a3, w.x, w.y);
            }
            if (s < 3) { vc0 = vn0; vc1 = vn1; }
        }
        // -------- node phase: s = 4..11 (fp16 direct), big GEMM only --------
        #pragma unroll
        for (int s4 = 0; s4 < 8; ++s4) {
            uint2 nn0, nn1;
            if (s4 < 7) {
                const int sp = s4 + 1;
                nn0 = __ldg((const uint2*)(nH + oN[sp >> 2][0] + (sp & 3) * 32));
                nn1 = __ldg((const uint2*)(nH + oN[sp >> 2][1] + (sp & 3) * 32));
            }
            const int ko = (s4 + 4) * 16 + 4 * t4;
            #pragma unroll
            for (int nt = 0; nt < 9; ++nt) {
                uint2 w = *(const uint2*)&swb[(nt * 8 + gq) * 208 + ko];
                mma_f16(accB[nt], nc0.x, nc1.x, nc0.y, nc1.y, w.x, w.y);
            }
            if (s4 < 7) { nc0 = nn0; nc1 = nn1; }
        }

        // ---------------- epilogue (registers only) ----------------
        #pragma unroll
        for (int hf = 0; hf < 2; ++hf) {
            const int h2  = hf * 2;
            const int row = hf * 8 + gq;

            float p[16], s1 = 0.f, s2 = 0.f;
            #pragma unroll
            for (int J = 0; J < 4; ++J) {
                float4 bm4 = *(const float4*)&sbm[J * 16 + t4 * 4];
                float pre[4] = { accB[2 * J][h2]     + bm4.x,
                                 accB[2 * J][h2 + 1] + bm4.y,
                                 accB[2 * J + 1][h2]     + bm4.z,
                                 accB[2 * J + 1][h2 + 1] + bm4.w };
                #pragma unroll
                for (int c = 0; c < 4; ++c) {
                    float th = 1.f - __fdividef(2.f, __expf(2.f * pre[c]) + 1.f);
                    p[J * 4 + c] = th;
                    s1 += th; s2 += th * th;
                }
            }
            s1 += __shfl_xor_sync(0xffffffffu, s1, 1);
            s1 += __shfl_xor_sync(0xffffffffu, s1, 2);
            s2 += __shfl_xor_sync(0xffffffffu, s2, 1);
            s2 += __shfl_xor_sync(0xffffffffu, s2, 2);
            float ap = accB[8][h2] + bma;
            ap = __shfl_sync(0xffffffffu, ap, lane & ~3);
            const float alpha = __fdividef(1.f, 1.f + __expf(-ap));
            const float mean  = s1 * (1.f / 64.f);
            const float var   = s2 * (1.f / 64.f) - mean * mean;
            const float rstd  = rsqrtf(var + LN_EPS) * alpha;

            float y[16], u1 = 0.f, u2 = 0.f;
            #pragma unroll
            for (int J = 0; J < 4; ++J) {
                float4 bi4 = *(const float4*)&sbi[J * 16 + t4 * 4];
                float y0 = accE[2 * J][h2]     + bi4.x + (p[J * 4 + 0] - mean) * rstd;
                float y1 = accE[2 * J][h2 + 1] + bi4.y + (p[J * 4 + 1] - mean) * rstd;
                float y2 = accE[2 * J + 1][h2]     + bi4.z + (p[J * 4 + 2] - mean) * rstd;
                float y3 = accE[2 * J + 1][h2 + 1] + bi4.w + (p[J * 4 + 3] - mean) * rstd;
                y[J * 4 + 0] = y0; y[J * 4 + 1] = y1; y[J * 4 + 2] = y2; y[J * 4 + 3] = y3;
                u1 += y0 + y1 + y2 + y3;
                u2 += y0 * y0 + y1 * y1 + y2 * y2 + y3 * y3;
            }
            u1 += __shfl_xor_sync(0xffffffffu, u1, 1);
            u1 += __shfl_xor_sync(0xffffffffu, u1, 2);
            u2 += __shfl_xor_sync(0xffffffffu, u2, 1);
            u2 += __shfl_xor_sync(0xffffffffu, u2, 2);
            const float m2  = u1 * (1.f / 64.f);
            const float v2  = u2 * (1.f / 64.f) - m2 * m2;
            const float rs2 = rsqrtf(v2 + LN_EPS);

            if (row < rem) {
                float* op = out + (size_t)(tb + row) * 64;
                #pragma unroll
                for (int J = 0; J < 4; ++J) {
                    float4 o;
                    o.x = (y[J * 4 + 0] - m2) * rs2;
                    o.y = (y[J * 4 + 1] - m2) * rs2;
                    o.z = (y[J * 4 + 2] - m2) * rs2;
                    o.w = (y[J * 4 + 3] - m2) * rs2;
                    __stcs((float4*)(op + J * 16 + t4 * 4), o);
                }
            }
        }
    }
}

extern "C" void kernel_launch(void* const* d_in, const int* in_sizes, int n_in,
                              void* d_out, int out_size)
{
    const float* node_fts = (const float*)d_in[0];
    const float* edge_fts = (const float*)d_in[1];
    const void*  edges    = d_in[2];
    const float* W_init   = (const float*)d_in[3];
    const float* b_init   = (const float*)d_in[4];
    const float* W_mlp    = (const float*)d_in[5];
    const float* b_mlp    = (const float*)d_in[6];
    const float* W_alpha  = (const float*)d_in[7];
    const float* b_alpha  = (const float*)d_in[8];
    float*       out      = (float*)d_out;

    const int n_edges = in_sizes[1] / 64;
    const int n_node4 = in_sizes[0] / 4;       // float4 count of node_fts
    const int ntiles  = (n_edges + 15) / 16;

    int nsm = 148;
    cudaDeviceGetAttribute(&nsm, cudaDevAttrMultiProcessorCount, 0);
    int need = (ntiles + 7) / 8;
    int maxg = 2 * nsm;
    int grid = need < maxg ? need : maxg;

    cudaFuncSetAttribute(edge_update_v11,
                         cudaFuncAttributeMaxDynamicSharedMemorySize, SMEM_BYTES);
    prep_all<<<74, 256>>>(W_init, b_init, W_mlp, b_mlp, W_alpha, b_alpha,
                          (const long long*)edges);
    prep_node<<<(n_node4 + 255) / 256, 256>>>(node_fts, n_node4);
    edge_update_v11<<<grid, NT, SMEM_BYTES>>>(edge_fts, edges, out, n_edges);
}

// round 13
// speedup vs baseline: 1.0955x; 1.0955x over previous
#include <cuda_runtime.h>
#include <cuda_fp16.h>
#include <cstdint>

#define NT 256
#define LN_EPS 1e-5f
#define MAX_NODES 100000

// smem byte offsets
#define SB_W1  0          // __half W1 packed: 64 cols x stride 80 halves  = 10240 B
#define SB_WB  10240      // __half Wbig packed: 72 cols x stride 208 halves = 29952 B
#define SB_BI  40192      // float b_init [64]
#define SB_BMX 40448      // float folded bias [65]+pad
#define SMEM_BYTES 40720

__device__ int    g_edges_is_i64;
__device__ __half g_w1[64 * 80];
__device__ __half g_wb[72 * 208];
__device__ float  g_bi[64];
__device__ float  g_bmx[68];
__device__ __half g_nodeh[MAX_NODES * 64];   // 12.8 MB fp16 node cache, K-permuted rows

// N-permutation: logical frag col -> actual col (thread's 16 cols = 4 float4s)
__device__ __host__ __forceinline__ int sigp(int c) {
    return 16 * (c >> 4) + 4 * ((c & 7) >> 1) + 2 * ((c >> 3) & 1) + (c & 1);
}

// single merged prep: node fp16 K-permuted cache + packed weights + biases + dtype probe
__global__ void prep_all(const float* __restrict__ node_fts, int n4,
                         const float* __restrict__ W_init,
                         const float* __restrict__ b_init,
                         const float* __restrict__ W_mlp,
                         const float* __restrict__ b_mlp,
                         const float* __restrict__ W_alpha,
                         const float* __restrict__ b_alpha,
                         const long long* __restrict__ e64)
{
    int i = blockIdx.x * blockDim.x + threadIdx.x;
    if (i == 0) {
        int ok = 1;
        for (int j = 0; j < 64; ++j) {
            long long v = e64[j];
            if (v < 0 || v >= (1LL << 31)) ok = 0;
        }
        g_edges_is_i64 = ok;
    }
    if (i < n4) {
        // node: float4 i4 of row; store 4 halves at permuted position
        int row = i >> 4, i4 = i & 15;
        float4 v = __ldg((const float4*)node_fts + i);
        __half2 h0 = __floats2half2_rn(v.x, v.y);
        __half2 h1 = __floats2half2_rn(v.z, v.w);
        uint2 u = { *(uint32_t*)&h0, *(uint32_t*)&h1 };
        // permuted half-offset: j=i4>>3 (step-pair), t4=i4&3, so=(i4>>2)&1
        int off = (i4 >> 3) * 32 + (i4 & 3) * 8 + ((i4 >> 2) & 1) * 4;
        *(uint2*)(g_nodeh + row * 64 + off) = u;
        return;
    }
    int j = i - n4;
    if (j < 64 * 64) {
        int c = j >> 6, k = j & 63;
        g_w1[c * 80 + k] = __float2half_rn(W_init[sigp(c) * 64 + k]);
    } else if (j < 64 * 64 + 72 * 192) {
        int j2 = j - 64 * 64;
        int c = j2 / 192, k = j2 - c * 192;
        float v = 0.f;
        if (c < 64) {
            int a = sigp(c);
            if (k < 64) {
                float s = 0.f;
                #pragma unroll 8
                for (int m = 0; m < 64; ++m) s += W_mlp[a * 192 + m] * W_init[m * 64 + k];
                v = s;
            } else v = W_mlp[a * 192 + k];
        } else if (c == 64) {
            if (k < 64) {
                float s = 0.f;
                #pragma unroll 8
                for (int m = 0; m < 64; ++m) s += W_alpha[m] * W_init[m * 64 + k];
                v = s;
            } else v = W_alpha[k];
        }
        g_wb[c * 208 + k] = __float2half_rn(v);
    } else if (j < 64 * 64 + 72 * 192 + 64) {
        int t = j - (64 * 64 + 72 * 192);
        g_bi[t] = b_init[t];
    } else if (j < 64 * 64 + 72 * 192 + 64 + 65) {
        int t = j - (64 * 64 + 72 * 192 + 64);
        float s = (t < 64) ? b_mlp[t] : b_alpha[0];
        const float* wr = (t < 64) ? (W_mlp + t * 192) : W_alpha;
        #pragma unroll 8
        for (int m = 0; m < 64; ++m) s += b_init[m] * wr[m];
        g_bmx[t] = s;
    }
}

__device__ __forceinline__ uint32_t H2(float a, float b) {
    __half2 h = __floats2half2_rn(a, b);
    return *(uint32_t*)&h;
}
__device__ __forceinline__ void mma_f16(float c[4], uint32_t a0, uint32_t a1, uint32_t a2,
                                        uint32_t a3, uint32_t b0, uint32_t b1) {
    asm volatile(
        "mma.sync.aligned.m16n8k16.row.col.f32.f16.f16.f32 "
        "{%0,%1,%2,%3}, {%4,%5,%6,%7}, {%8,%9}, {%0,%1,%2,%3};\n"
        : "+f"(c[0]), "+f"(c[1]), "+f"(c[2]), "+f"(c[3])
        : "r"(a0), "r"(a1), "r"(a2), "r"(a3), "r"(b0), "r"(b1));
}

__global__ void __launch_bounds__(NT, 2)
edge_update_v12(const float* __restrict__ edge_fts,
                const void* __restrict__ edges_raw,
                float* __restrict__ out,
                int n_edges)
{
    extern __shared__ char smc[];
    const int tid = threadIdx.x;
    {
        int4* d = (int4*)smc;
        const int4* s1 = (const int4*)g_w1;
        for (int i = tid; i < 10240 / 16; i += NT) d[i] = s1[i];
        int4* d2 = (int4*)(smc + SB_WB);
        const int4* s2 = (const int4*)g_wb;
        for (int i = tid; i < 29952 / 16; i += NT) d2[i] = s2[i];
        float* bf = (float*)(smc + SB_BI);
        if (tid < 64) bf[tid] = g_bi[tid];
        float* bm = (float*)(smc + SB_BMX);
        if (tid < 65) bm[tid] = g_bmx[tid];
    }
    __syncthreads();

    const __half* sw1 = (const __half*)(smc + SB_W1);
    const __half* swb = (const __half*)(smc + SB_WB);
    const float*  sbi = (const float*)(smc + SB_BI);
    const float*  sbm = (const float*)(smc + SB_BMX);

    const int wid  = tid >> 5;
    const int lane = tid & 31;
    const int gq   = lane >> 2;
    const int t4   = lane & 3;
    const int is64 = g_edges_is_i64;
    const long long* e64 = (const long long*)edges_raw;
    const int*       e32 = (const int*)edges_raw;
    const float bma = sbm[64];

    const char* eB = (const char*)edge_fts;
    const char* nH = (const char*)g_nodeh;
    const int ntiles = (n_edges + 15) >> 4;

    for (int wt = blockIdx.x * 8 + wid; wt < ntiles; wt += gridDim.x * 8) {
        const int tb  = wt << 4;
        const int rem = min(16, n_edges - tb);

        int hidx = 0, tidx = 0;
        if (lane < 16) {
            size_t ep = (size_t)min(tb + lane, n_edges - 1);
            if (is64) { hidx = (int)e64[ep]; tidx = (int)e64[ep + (size_t)n_edges]; }
            else      { hidx = e32[ep];      tidx = e32[ep + (size_t)n_edges]; }
        }
        // edge row pointers (fp32, 256B rows); node byte offsets (fp16 permuted, 128B rows)
        const char* pE[2];
        uint32_t oN[2][2];                     // [head/tail][row-chunk]
        #pragma unroll
        for (int r = 0; r < 2; ++r) {
            const int row = r * 8 + gq;
            const int er  = min(tb + row, n_edges - 1);
            pE[r] = eB + (size_t)er * 256 + (size_t)(t4 * 16);
            const int hi = __shfl_sync(0xffffffffu, hidx, row);
            const int ti = __shfl_sync(0xffffffffu, tidx, row);
            oN[0][r] = (uint32_t)hi * 128u + (uint32_t)(t4 * 16);
            oN[1][r] = (uint32_t)ti * 128u + (uint32_t)(t4 * 16);
        }

        float accE[8][4], accB[9][4];
        #pragma unroll
        for (int b = 0; b < 8; ++b)
            #pragma unroll
            for (int c = 0; c < 4; ++c) accE[b][c] = 0.f;
        #pragma unroll
        for (int b = 0; b < 9; ++b)
            #pragma unroll
            for (int c = 0; c < 4; ++c) accB[b][c] = 0.f;

        // -------- edge phase: s = 0..3 (fp32 load + cvt), both GEMMs --------
        float4 vc0 = __ldg((const float4*)pE[0]);
        float4 vc1 = __ldg((const float4*)pE[1]);
        uint4 cc0, cc1;                        // node step-pair preload
        #pragma unroll
        for (int s = 0; s < 4; ++s) {
            float4 vn0, vn1;
            if (s < 3) {
                vn0 = __ldg((const float4*)(pE[0] + (s + 1) * 64));
                vn1 = __ldg((const float4*)(pE[1] + (s + 1) * 64));
            } else {
                cc0 = __ldg((const uint4*)(nH + oN[0][0]));   // head pair j=0, chunk0
                cc1 = __ldg((const uint4*)(nH + oN[0][1]));   // chunk1
            }
            const uint32_t a0 = H2(vc0.x, vc0.y), a1 = H2(vc1.x, vc1.y);
            const uint32_t a2 = H2(vc0.z, vc0.w), a3 = H2(vc1.z, vc1.w);
            const int ko = s * 16 + 4 * t4;
            #pragma unroll
            for (int nt = 0; nt < 9; ++nt) {
                uint2 w = *(const uint2*)&swb[(nt * 8 + gq) * 208 + ko];
                mma_f16(accB[nt], a0, a1, a2, a3, w.x, w.y);
            }
            #pragma unroll
            for (int nt = 0; nt < 8; ++nt) {
                uint2 w = *(const uint2*)&sw1[(nt * 8 + gq) * 80 + ko];
                mma_f16(accE[nt], a0, a1, a2, a3, w.x, w.y);
            }
            if (s < 3) { vc0 = vn0; vc1 = vn1; }
        }
        // -------- node phase: 4 step-pairs (head j=0,1 ; tail j=0,1), big GEMM only --------
        #pragma unroll
        for (int pj = 0; pj < 4; ++pj) {
            uint4 nn0, nn1;
            if (pj < 3) {
                const int np = pj + 1;
                nn0 = __ldg((const uint4*)(nH + oN[np >> 1][0] + (np & 1) * 64));
                nn1 = __ldg((const uint4*)(nH + oN[np >> 1][1] + (np & 1) * 64));
            }
            // step 2pj (global 4+2pj): fragments from .x/.y
            {
                const int ko = (4 + 2 * pj) * 16 + 4 * t4;
                #pragma unroll
                for (int nt = 0; nt < 9; ++nt) {
                    uint2 w = *(const uint2*)&swb[(nt * 8 + gq) * 208 + ko];
                    mma_f16(accB[nt], cc0.x, cc1.x, cc0.y, cc1.y, w.x, w.y);
                }
            }
            // step 2pj+1: fragments from .z/.w
            {
                const int ko = (5 + 2 * pj) * 16 + 4 * t4;
                #pragma unroll
                for (int nt = 0; nt < 9; ++nt) {
                    uint2 w = *(const uint2*)&swb[(nt * 8 + gq) * 208 + ko];
                    mma_f16(accB[nt], cc0.z, cc1.z, cc0.w, cc1.w, w.x, w.y);
                }
            }
            if (pj < 3) { cc0 = nn0; cc1 = nn1; }
        }

        // ---------------- epilogue (registers only) ----------------
        #pragma unroll
        for (int hf = 0; hf < 2; ++hf) {
            const int h2  = hf * 2;
            const int row = hf * 8 + gq;

            float p[16], s1 = 0.f, s2 = 0.f;
            #pragma unroll
            for (int J = 0; J < 4; ++J) {
                float4 bm4 = *(const float4*)&sbm[J * 16 + t4 * 4];
                float pre[4] = { accB[2 * J][h2]     + bm4.x,
                                 accB[2 * J][h2 + 1] + bm4.y,
                                 accB[2 * J + 1][h2]     + bm4.z,
                                 accB[2 * J + 1][h2 + 1] + bm4.w };
                #pragma unroll
                for (int c = 0; c < 4; ++c) {
                    float th = 1.f - __fdividef(2.f, __expf(2.f * pre[c]) + 1.f);
                    p[J * 4 + c] = th;
                    s1 += th; s2 += th * th;
                }
            }
            s1 += __shfl_xor_sync(0xffffffffu, s1, 1);
            s1 += __shfl_xor_sync(0xffffffffu, s1, 2);
            s2 += __shfl_xor_sync(0xffffffffu, s2, 1);
            s2 += __shfl_xor_sync(0xffffffffu, s2, 2);
            float ap = accB[8][h2] + bma;
            ap = __shfl_sync(0xffffffffu, ap, lane & ~3);
            const float alpha = __fdividef(1.f, 1.f + __expf(-ap));
            const float mean  = s1 * (1.f / 64.f);
            const float var   = s2 * (1.f / 64.f) - mean * mean;
            const float rstd  = rsqrtf(var + LN_EPS) * alpha;

            float y[16], u1 = 0.f, u2 = 0.f;
            #pragma unroll
            for (int J = 0; J < 4; ++J) {
                float4 bi4 = *(const float4*)&sbi[J * 16 + t4 * 4];
                float y0 = accE[2 * J][h2]     + bi4.x + (p[J * 4 + 0] - mean) * rstd;
                float y1 = accE[2 * J][h2 + 1] + bi4.y + (p[J * 4 + 1] - mean) * rstd;
                float y2 = accE[2 * J + 1][h2]     + bi4.z + (p[J * 4 + 2] - mean) * rstd;
                float y3 = accE[2 * J + 1][h2 + 1] + bi4.w + (p[J * 4 + 3] - mean) * rstd;
                y[J * 4 + 0] = y0; y[J * 4 + 1] = y1; y[J * 4 + 2] = y2; y[J * 4 + 3] = y3;
                u1 += y0 + y1 + y2 + y3;
                u2 += y0 * y0 + y1 * y1 + y2 * y2 + y3 * y3;
            }
            u1 += __shfl_xor_sync(0xffffffffu, u1, 1);
            u1 += __shfl_xor_sync(0xffffffffu, u1, 2);
            u2 += __shfl_xor_sync(0xffffffffu, u2, 1);
            u2 += __shfl_xor_sync(0xffffffffu, u2, 2);
            const float m2  = u1 * (1.f / 64.f);
            const float v2  = u2 * (1.f / 64.f) - m2 * m2;
            const float rs2 = rsqrtf(v2 + LN_EPS);

            if (row < rem) {
                float* op = out + (size_t)(tb + row) * 64;
                #pragma unroll
                for (int J = 0; J < 4; ++J) {
                    float4 o;
                    o.x = (y[J * 4 + 0] - m2) * rs2;
                    o.y = (y[J * 4 + 1] - m2) * rs2;
                    o.z = (y[J * 4 + 2] - m2) * rs2;
                    o.w = (y[J * 4 + 3] - m2) * rs2;
                    __stcs((float4*)(op + J * 16 + t4 * 4), o);
                }
            }
        }
    }
}

extern "C" void kernel_launch(void* const* d_in, const int* in_sizes, int n_in,
                              void* d_out, int out_size)
{
    const float* node_fts = (const float*)d_in[0];
    const float* edge_fts = (const float*)d_in[1];
    const void*  edges    = d_in[2];
    const float* W_init   = (const float*)d_in[3];
    const float* b_init   = (const float*)d_in[4];
    const float* W_mlp    = (const float*)d_in[5];
    const float* b_mlp    = (const float*)d_in[6];
    const float* W_alpha  = (const float*)d_in[7];
    const float* b_alpha  = (const float*)d_in[8];
    float*       out      = (float*)d_out;

    const int n_edges = in_sizes[1] / 64;
    const int n4      = in_sizes[0] / 4;       // node float4 count
    const int ntiles  = (n_edges + 15) / 16;

    int nsm = 148;
    cudaDeviceGetAttribute(&nsm, cudaDevAttrMultiProcessorCount, 0);
    int need = (ntiles + 7) / 8;
    int maxg = 2 * nsm;
    int grid = need < maxg ? need : maxg;

    const int prep_threads = n4 + 64 * 64 + 72 * 192 + 64 + 65;

    cudaFuncSetAttribute(edge_update_v12,
                         cudaFuncAttributeMaxDynamicSharedMemorySize, SMEM_BYTES);
    prep_all<<<(prep_threads + 255) / 256, 256>>>(node_fts, n4, W_init, b_init,
                                                  W_mlp, b_mlp, W_alpha, b_alpha,
                                                  (const long long*)edges);
    edge_update_v12<<<grid, NT, SMEM_BYTES>>>(edge_fts, edges, out, n_edges);
}

// round 14
// speedup vs baseline: 1.1572x; 1.0563x over previous
#include <cuda_runtime.h>
#include <cuda_fp16.h>
#include <cstdint>

#define NT 256
#define LN_EPS 1e-5f
#define MAX_NODES 100000

// smem byte offsets
#define SB_W1  0          // __half W1 packed: 64 cols x stride 80 halves  = 10240 B
#define SB_WB  10240      // __half Wbig packed: 72 cols x stride 208 halves = 29952 B
#define SB_BI  40192      // float b_init [64]
#define SB_BMX 40448      // float folded bias [65]+pad
#define SMEM_BYTES 40720

__device__ int    g_edges_is_i64;
__device__ __half g_w1[64 * 80];
__device__ __half g_wb[72 * 208];
__device__ float  g_bi[64];
__device__ float  g_bmx[68];
__device__ __half g_nodeh[MAX_NODES * 64];   // 12.8 MB fp16 node cache, K-permuted rows

// N-permutation: logical frag col -> actual col (thread's 16 cols = 4 float4s)
__device__ __host__ __forceinline__ int sigp(int c) {
    return 16 * (c >> 4) + 4 * ((c & 7) >> 1) + 2 * ((c >> 3) & 1) + (c & 1);
}

// single merged prep: node fp16 K-permuted cache + packed weights + biases + dtype probe
__global__ void prep_all(const float* __restrict__ node_fts, int n4,
                         const float* __restrict__ W_init,
                         const float* __restrict__ b_init,
                         const float* __restrict__ W_mlp,
                         const float* __restrict__ b_mlp,
                         const float* __restrict__ W_alpha,
                         const float* __restrict__ b_alpha,
                         const long long* __restrict__ e64)
{
    int i = blockIdx.x * blockDim.x + threadIdx.x;
    if (i == 0) {
        int ok = 1;
        for (int j = 0; j < 64; ++j) {
            long long v = e64[j];
            if (v < 0 || v >= (1LL << 31)) ok = 0;
        }
        g_edges_is_i64 = ok;
    }
    if (i < n4) {
        int row = i >> 4, i4 = i & 15;
        float4 v = __ldg((const float4*)node_fts + i);
        __half2 h0 = __floats2half2_rn(v.x, v.y);
        __half2 h1 = __floats2half2_rn(v.z, v.w);
        uint2 u = { *(uint32_t*)&h0, *(uint32_t*)&h1 };
        int off = (i4 >> 3) * 32 + (i4 & 3) * 8 + ((i4 >> 2) & 1) * 4;
        *(uint2*)(g_nodeh + row * 64 + off) = u;
        return;
    }
    int j = i - n4;
    if (j < 64 * 64) {
        int c = j >> 6, k = j & 63;
        g_w1[c * 80 + k] = __float2half_rn(W_init[sigp(c) * 64 + k]);
    } else if (j < 64 * 64 + 72 * 192) {
        int j2 = j - 64 * 64;
        int c = j2 / 192, k = j2 - c * 192;
        float v = 0.f;
        if (c < 64) {
            int a = sigp(c);
            if (k < 64) {
                float s = 0.f;
                #pragma unroll 8
                for (int m = 0; m < 64; ++m) s += W_mlp[a * 192 + m] * W_init[m * 64 + k];
                v = s;
            } else v = W_mlp[a * 192 + k];
        } else if (c == 64) {
            if (k < 64) {
                float s = 0.f;
                #pragma unroll 8
                for (int m = 0; m < 64; ++m) s += W_alpha[m] * W_init[m * 64 + k];
                v = s;
            } else v = W_alpha[k];
        }
        g_wb[c * 208 + k] = __float2half_rn(v);
    } else if (j < 64 * 64 + 72 * 192 + 64) {
        int t = j - (64 * 64 + 72 * 192);
        g_bi[t] = b_init[t];
    } else if (j < 64 * 64 + 72 * 192 + 64 + 65) {
        int t = j - (64 * 64 + 72 * 192 + 64);
        float s = (t < 64) ? b_mlp[t] : b_alpha[0];
        const float* wr = (t < 64) ? (W_mlp + t * 192) : W_alpha;
        #pragma unroll 8
        for (int m = 0; m < 64; ++m) s += b_init[m] * wr[m];
        g_bmx[t] = s;
    }
}

__device__ __forceinline__ uint32_t H2(float a, float b) {
    __half2 h = __floats2half2_rn(a, b);
    return *(uint32_t*)&h;
}
__device__ __forceinline__ void mma_f16(float c[4], uint32_t a0, uint32_t a1, uint32_t a2,
                                        uint32_t a3, uint32_t b0, uint32_t b1) {
    asm volatile(
        "mma.sync.aligned.m16n8k16.row.col.f32.f16.f16.f32 "
        "{%0,%1,%2,%3}, {%4,%5,%6,%7}, {%8,%9}, {%0,%1,%2,%3};\n"
        : "+f"(c[0]), "+f"(c[1]), "+f"(c[2]), "+f"(c[3])
        : "r"(a0), "r"(a1), "r"(a2), "r"(a3), "r"(b0), "r"(b1));
}

__global__ void __launch_bounds__(NT, 2)
edge_update_v14(const float* __restrict__ edge_fts,
                const void* __restrict__ edges_raw,
                float* __restrict__ out,
                int n_edges)
{
    extern __shared__ char smc[];
    const int tid = threadIdx.x;
    {
        int4* d = (int4*)smc;
        const int4* s1 = (const int4*)g_w1;
        for (int i = tid; i < 10240 / 16; i += NT) d[i] = s1[i];
        int4* d2 = (int4*)(smc + SB_WB);
        const int4* s2 = (const int4*)g_wb;
        for (int i = tid; i < 29952 / 16; i += NT) d2[i] = s2[i];
        float* bf = (float*)(smc + SB_BI);
        if (tid < 64) bf[tid] = g_bi[tid];
        float* bm = (float*)(smc + SB_BMX);
        if (tid < 65) bm[tid] = g_bmx[tid];
    }
    __syncthreads();

    const __half* sw1 = (const __half*)(smc + SB_W1);
    const __half* swb = (const __half*)(smc + SB_WB);
    const float*  sbi = (const float*)(smc + SB_BI);
    const float*  sbm = (const float*)(smc + SB_BMX);

    const int wid  = tid >> 5;
    const int lane = tid & 31;
    const int gq   = lane >> 2;
    const int t4   = lane & 3;
    const int is64 = g_edges_is_i64;
    const long long* e64 = (const long long*)edges_raw;
    const int*       e32 = (const int*)edges_raw;
    const float bma = sbm[64];

    const char* eB = (const char*)edge_fts;
    const char* nH = (const char*)g_nodeh;
    const int ntiles  = (n_edges + 15) >> 4;
    const int wstride = gridDim.x * 8;

#define LOADIDX(dh, dt, tw) do { \
        size_t ep = (size_t)min(((tw) << 4) + lane, n_edges - 1); \
        if (is64) { dh = (int)e64[ep]; dt = (int)e64[ep + (size_t)n_edges]; } \
        else      { dh = e32[ep];      dt = e32[ep + (size_t)n_edges]; } \
    } while (0)

#define SETPTRS(PE0, PE1, OH0, OH1, OT0, OT1, HI, TI, tw) do { \
        { const int er0 = min(((tw) << 4) + gq,     n_edges - 1); \
          const int er1 = min(((tw) << 4) + 8 + gq, n_edges - 1); \
          PE0 = eB + (size_t)er0 * 256 + (size_t)(t4 * 16); \
          PE1 = eB + (size_t)er1 * 256 + (size_t)(t4 * 16); } \
        { const int h0 = __shfl_sync(0xffffffffu, HI, gq); \
          const int h1 = __shfl_sync(0xffffffffu, HI, 8 + gq); \
          const int tt0 = __shfl_sync(0xffffffffu, TI, gq); \
          const int tt1 = __shfl_sync(0xffffffffu, TI, 8 + gq); \
          OH0 = (uint32_t)h0 * 128u + (uint32_t)(t4 * 16); \
          OH1 = (uint32_t)h1 * 128u + (uint32_t)(t4 * 16); \
          OT0 = (uint32_t)tt0 * 128u + (uint32_t)(t4 * 16); \
          OT1 = (uint32_t)tt1 * 128u + (uint32_t)(t4 * 16); } \
    } while (0)

    int wt = blockIdx.x * 8 + wid;
    if (wt >= ntiles) return;

    // ---------------- prologue: tile-0 state ----------------
    int hidx, tidx;
    const char *pE0, *pE1;
    uint32_t oH0, oH1, oT0, oT1;
    LOADIDX(hidx, tidx, wt);
    SETPTRS(pE0, pE1, oH0, oH1, oT0, oT1, hidx, tidx, wt);
    float4 vc0 = __ldg((const float4*)pE0);
    float4 vc1 = __ldg((const float4*)pE1);
    uint4  cc0 = __ldg((const uint4*)(nH + oH0));
    uint4  cc1 = __ldg((const uint4*)(nH + oH1));

    for (; wt < ntiles; wt += wstride) {
        const int tb  = wt << 4;
        const int rem = min(16, n_edges - tb);
        const int wtn = min(wt + wstride, ntiles - 1);

        // early: next tile's gather indices (consumed far later)
        int hidxN, tidxN;
        LOADIDX(hidxN, tidxN, wtn);

        float accE[8][4], accB[9][4];
        #pragma unroll
        for (int b = 0; b < 8; ++b)
            #pragma unroll
            for (int c = 0; c < 4; ++c) accE[b][c] = 0.f;
        #pragma unroll
        for (int b = 0; b < 9; ++b)
            #pragma unroll
            for (int c = 0; c < 4; ++c) accB[b][c] = 0.f;

        // -------- edge phase: s = 0..3, both GEMMs (node cc already in flight) --------
        #pragma unroll
        for (int s = 0; s < 4; ++s) {
            float4 vn0, vn1;
            if (s < 3) {
                vn0 = __ldg((const float4*)(pE0 + (s + 1) * 64));
                vn1 = __ldg((const float4*)(pE1 + (s + 1) * 64));
            }
            const uint32_t a0 = H2(vc0.x, vc0.y), a1 = H2(vc1.x, vc1.y);
            const uint32_t a2 = H2(vc0.z, vc0.w), a3 = H2(vc1.z, vc1.w);
            const int ko = s * 16 + 4 * t4;
            #pragma unroll
            for (int nt = 0; nt < 9; ++nt) {
                uint2 w = *(const uint2*)&swb[(nt * 8 + gq) * 208 + ko];
                mma_f16(accB[nt], a0, a1, a2, a3, w.x, w.y);
            }
            #pragma unroll
            for (int nt = 0; nt < 8; ++nt) {
                uint2 w = *(const uint2*)&sw1[(nt * 8 + gq) * 80 + ko];
                mma_f16(accE[nt], a0, a1, a2, a3, w.x, w.y);
            }
            if (s < 3) { vc0 = vn0; vc1 = vn1; }
        }

        // pack e (+b_init) to fp16 — frees 16 registers for the cross-tile prefetch
        uint32_t eh[2][8];
        #pragma unroll
        for (int hf = 0; hf < 2; ++hf) {
            const int h2 = hf * 2;
            #pragma unroll
            for (int J = 0; J < 4; ++J) {
                float4 bi4 = *(const float4*)&sbi[J * 16 + t4 * 4];
                eh[hf][J * 2]     = H2(accE[2 * J][h2] + bi4.x,     accE[2 * J][h2 + 1] + bi4.y);
                eh[hf][J * 2 + 1] = H2(accE[2 * J + 1][h2] + bi4.z, accE[2 * J + 1][h2 + 1] + bi4.w);
            }
        }

        // -------- node phase: 4 step-pairs (head j0,j1 ; tail j0,j1) --------
        #pragma unroll
        for (int pj = 0; pj < 4; ++pj) {
            uint4 nn0, nn1;
            if (pj < 3) {
                const int np = pj + 1;
                const uint32_t b0 = (np >> 1) ? oT0 : oH0;
                const uint32_t b1 = (np >> 1) ? oT1 : oH1;
                nn0 = __ldg((const uint4*)(nH + b0 + (np & 1) * 64));
                nn1 = __ldg((const uint4*)(nH + b1 + (np & 1) * 64));
            }
            {
                const int ko = (4 + 2 * pj) * 16 + 4 * t4;
                #pragma unroll
                for (int nt = 0; nt < 9; ++nt) {
                    uint2 w = *(const uint2*)&swb[(nt * 8 + gq) * 208 + ko];
                    mma_f16(accB[nt], cc0.x, cc1.x, cc0.y, cc1.y, w.x, w.y);
                }
            }
            {
                const int ko = (5 + 2 * pj) * 16 + 4 * t4;
                #pragma unroll
                for (int nt = 0; nt < 9; ++nt) {
                    uint2 w = *(const uint2*)&swb[(nt * 8 + gq) * 208 + ko];
                    mma_f16(accB[nt], cc0.z, cc1.z, cc0.w, cc1.w, w.x, w.y);
                }
            }
            if (pj < 3) { cc0 = nn0; cc1 = nn1; }
        }

        // -------- prefetch next tile across the epilogue --------
        const char *pE0n, *pE1n;
        uint32_t oH0n, oH1n, oT0n, oT1n;
        SETPTRS(pE0n, pE1n, oH0n, oH1n, oT0n, oT1n, hidxN, tidxN, wtn);
        float4 vc0n = __ldg((const float4*)pE0n);
        float4 vc1n = __ldg((const float4*)pE1n);
        uint4  cc0n = __ldg((const uint4*)(nH + oH0n));
        uint4  cc1n = __ldg((const uint4*)(nH + oH1n));

        // ---------------- epilogue (registers only) ----------------
        #pragma unroll
        for (int hf = 0; hf < 2; ++hf) {
            const int h2  = hf * 2;
            const int row = hf * 8 + gq;

            float p[16], s1 = 0.f, s2 = 0.f;
            #pragma unroll
            for (int J = 0; J < 4; ++J) {
                float4 bm4 = *(const float4*)&sbm[J * 16 + t4 * 4];
                float pre[4] = { accB[2 * J][h2]     + bm4.x,
                                 accB[2 * J][h2 + 1] + bm4.y,
                                 accB[2 * J + 1][h2]     + bm4.z,
                                 accB[2 * J + 1][h2 + 1] + bm4.w };
                #pragma unroll
                for (int c = 0; c < 4; ++c) {
                    float th = 1.f - __fdividef(2.f, __expf(2.f * pre[c]) + 1.f);
                    p[J * 4 + c] = th;
                    s1 += th; s2 += th * th;
                }
            }
            s1 += __shfl_xor_sync(0xffffffffu, s1, 1);
            s1 += __shfl_xor_sync(0xffffffffu, s1, 2);
            s2 += __shfl_xor_sync(0xffffffffu, s2, 1);
            s2 += __shfl_xor_sync(0xffffffffu, s2, 2);
            float ap = accB[8][h2] + bma;
            ap = __shfl_sync(0xffffffffu, ap, lane & ~3);
            const float alpha = __fdividef(1.f, 1.f + __expf(-ap));
            const float mean  = s1 * (1.f / 64.f);
            const float var   = s2 * (1.f / 64.f) - mean * mean;
            const float rstd  = rsqrtf(var + LN_EPS) * alpha;

            float y[16], u1 = 0.f, u2 = 0.f;
            #pragma unroll
            for (int J = 0; J < 4; ++J) {
                float2 e01 = __half22float2(*(__half2*)&eh[hf][J * 2]);
                float2 e23 = __half22float2(*(__half2*)&eh[hf][J * 2 + 1]);
                float y0 = e01.x + (p[J * 4 + 0] - mean) * rstd;
                float y1 = e01.y + (p[J * 4 + 1] - mean) * rstd;
                float y2 = e23.x + (p[J * 4 + 2] - mean) * rstd;
                float y3 = e23.y + (p[J * 4 + 3] - mean) * rstd;
                y[J * 4 + 0] = y0; y[J * 4 + 1] = y1; y[J * 4 + 2] = y2; y[J * 4 + 3] = y3;
                u1 += y0 + y1 + y2 + y3;
                u2 += y0 * y0 + y1 * y1 + y2 * y2 + y3 * y3;
            }
            u1 += __shfl_xor_sync(0xffffffffu, u1, 1);
            u1 += __shfl_xor_sync(0xffffffffu, u1, 2);
            u2 += __shfl_xor_sync(0xffffffffu, u2, 1);
            u2 += __shfl_xor_sync(0xffffffffu, u2, 2);
            const float m2  = u1 * (1.f / 64.f);
            const float v2  = u2 * (1.f / 64.f) - m2 * m2;
            const float rs2 = rsqrtf(v2 + LN_EPS);

            if (row < rem) {
                float* op = out + (size_t)(tb + row) * 64;
                #pragma unroll
                for (int J = 0; J < 4; ++J) {
                    float4 o;
                    o.x = (y[J * 4 + 0] - m2) * rs2;
                    o.y = (y[J * 4 + 1] - m2) * rs2;
                    o.z = (y[J * 4 + 2] - m2) * rs2;
                    o.w = (y[J * 4 + 3] - m2) * rs2;
                    __stcs((float4*)(op + J * 16 + t4 * 4), o);
                }
            }
        }

        // rotate pipeline state
        pE0 = pE0n; pE1 = pE1n;
        oH0 = oH0n; oH1 = oH1n; oT0 = oT0n; oT1 = oT1n;
        vc0 = vc0n; vc1 = vc1n; cc0 = cc0n; cc1 = cc1n;
    }
#undef LOADIDX
#undef SETPTRS
}

extern "C" void kernel_launch(void* const* d_in, const int* in_sizes, int n_in,
                              void* d_out, int out_size)
{
    const float* node_fts = (const float*)d_in[0];
    const float* edge_fts = (const float*)d_in[1];
    const void*  edges    = d_in[2];
    const float* W_init   = (const float*)d_in[3];
    const float* b_init   = (const float*)d_in[4];
    const float* W_mlp    = (const float*)d_in[5];
    const float* b_mlp    = (const float*)d_in[6];
    const float* W_alpha  = (const float*)d_in[7];
    const float* b_alpha  = (const float*)d_in[8];
    float*       out      = (float*)d_out;

    const int n_edges = in_sizes[1] / 64;
    const int n4      = in_sizes[0] / 4;
    const int ntiles  = (n_edges + 15) / 16;

    int nsm = 148;
    cudaDeviceGetAttribute(&nsm, cudaDevAttrMultiProcessorCount, 0);
    int need = (ntiles + 7) / 8;
    int maxg = 2 * nsm;
    int grid = need < maxg ? need : maxg;

    const int prep_threads = n4 + 64 * 64 + 72 * 192 + 64 + 65;

    cudaFuncSetAttribute(edge_update_v14,
                         cudaFuncAttributeMaxDynamicSharedMemorySize, SMEM_BYTES);
    prep_all<<<(prep_threads + 255) / 256, 256>>>(node_fts, n4, W_init, b_init,
                                                  W_mlp, b_mlp, W_alpha, b_alpha,
                                                  (const long long*)edges);
    edge_update_v14<<<grid, NT, SMEM_BYTES>>>(edge_fts, edges, out, n_edges);
}

// round 15
// speedup vs baseline: 1.1665x; 1.0081x over previous
#include <cuda_runtime.h>
#include <cuda_fp16.h>
#include <cstdint>

#define NT 256
#define LN_EPS 1e-5f
#define MAX_NODES 100000

// smem byte offsets (fragment-major weights: slot (s,lane) stride 80 B)
#define SB_W1  0          // 4 s  x 32 lanes x 80 B = 10240
#define SB_WB  10240      // 12 s x 32 lanes x 80 B = 30720
#define SB_BI  40960      // float b_init [64]
#define SB_BMX 41216      // float folded bias [65]+pad
#define SMEM_BYTES 41488

__device__ int    g_edges_is_i64;
__device__ __half g_w1[4 * 32 * 40];
__device__ __half g_wb[12 * 32 * 40];
__device__ float  g_bi[64];
__device__ float  g_bmx[68];
__device__ __half g_nodeh[MAX_NODES * 64];   // fp16 node cache, K-permuted rows

__device__ __host__ __forceinline__ int sigp(int c) {
    return 16 * (c >> 4) + 4 * ((c & 7) >> 1) + 2 * ((c >> 3) & 1) + (c & 1);
}

__global__ void prep_all(const float* __restrict__ node_fts, int n4,
                         const float* __restrict__ W_init,
                         const float* __restrict__ b_init,
                         const float* __restrict__ W_mlp,
                         const float* __restrict__ b_mlp,
                         const float* __restrict__ W_alpha,
                         const float* __restrict__ b_alpha,
                         const long long* __restrict__ e64)
{
    int i = blockIdx.x * blockDim.x + threadIdx.x;
    if (i == 0) {
        int ok = 1;
        for (int j = 0; j < 64; ++j) {
            long long v = e64[j];
            if (v < 0 || v >= (1LL << 31)) ok = 0;
        }
        g_edges_is_i64 = ok;
    }
    if (i < n4) {
        int row = i >> 4, i4 = i & 15;
        float4 v = __ldg((const float4*)node_fts + i);
        __half2 h0 = __floats2half2_rn(v.x, v.y);
        __half2 h1 = __floats2half2_rn(v.z, v.w);
        uint2 u = { *(uint32_t*)&h0, *(uint32_t*)&h1 };
        int off = (i4 >> 3) * 32 + (i4 & 3) * 8 + ((i4 >> 2) & 1) * 4;
        *(uint2*)(g_nodeh + row * 64 + off) = u;
        return;
    }
    int j = i - n4;
    if (j < 64 * 64) {
        // W1 fragment-major: logical col c (0..63), k (0..63)
        int c = j >> 6, k = j & 63;
        int nt = c >> 3, gq = c & 7;
        int s = k >> 4, t4 = (k & 15) >> 2, r = k & 3;
        int lane = gq * 4 + t4;
        g_w1[(s * 32 + lane) * 40 + nt * 4 + r] = __float2half_rn(W_init[sigp(c) * 64 + k]);
    } else if (j < 64 * 64 + 72 * 192) {
        int j2 = j - 64 * 64;
        int c = j2 / 192, k = j2 - c * 192;
        float v = 0.f;
        if (c < 64) {
            int a = sigp(c);
            if (k < 64) {
                float s = 0.f;
                #pragma unroll 8
                for (int m = 0; m < 64; ++m) s += W_mlp[a * 192 + m] * W_init[m * 64 + k];
                v = s;
            } else v = W_mlp[a * 192 + k];
        } else if (c == 64) {
            if (k < 64) {
                float s = 0.f;
                #pragma unroll 8
                for (int m = 0; m < 64; ++m) s += W_alpha[m] * W_init[m * 64 + k];
                v = s;
            } else v = W_alpha[k];
        }
        int nt = c >> 3, gq = c & 7;
        int s = k >> 4, t4 = (k & 15) >> 2, r = k & 3;
        int lane = gq * 4 + t4;
        g_wb[(s * 32 + lane) * 40 + nt * 4 + r] = __float2half_rn(v);
    } else if (j < 64 * 64 + 72 * 192 + 64) {
        int t = j - (64 * 64 + 72 * 192);
        g_bi[t] = b_init[t];
    } else if (j < 64 * 64 + 72 * 192 + 64 + 65) {
        int t = j - (64 * 64 + 72 * 192 + 64);
        float s = (t < 64) ? b_mlp[t] : b_alpha[0];
        const float* wr = (t < 64) ? (W_mlp + t * 192) : W_alpha;
        #pragma unroll 8
        for (int m = 0; m < 64; ++m) s += b_init[m] * wr[m];
        g_bmx[t] = s;
    }
}

__device__ __forceinline__ uint32_t H2(float a, float b) {
    __half2 h = __floats2half2_rn(a, b);
    return *(uint32_t*)&h;
}
__device__ __forceinline__ float tanhap(float x) {
    float r; asm("tanh.approx.f32 %0, %1;" : "=f"(r) : "f"(x));
    return r;
}
__device__ __forceinline__ void mma_f16(float c[4], uint32_t a0, uint32_t a1, uint32_t a2,
                                        uint32_t a3, uint32_t b0, uint32_t b1) {
    asm volatile(
        "mma.sync.aligned.m16n8k16.row.col.f32.f16.f16.f32 "
        "{%0,%1,%2,%3}, {%4,%5,%6,%7}, {%8,%9}, {%0,%1,%2,%3};\n"
        : "+f"(c[0]), "+f"(c[1]), "+f"(c[2]), "+f"(c[3])
        : "r"(a0), "r"(a1), "r"(a2), "r"(a3), "r"(b0), "r"(b1));
}

__global__ void __launch_bounds__(NT, 2)
edge_update_v15(const float* __restrict__ edge_fts,
                const void* __restrict__ edges_raw,
                float* __restrict__ out,
                int n_edges)
{
    extern __shared__ char smc[];
    const int tid = threadIdx.x;
    {
        int4* d1 = (int4*)smc;
        const int4* s1 = (const int4*)g_w1;
        for (int i = tid; i < 10240 / 16; i += NT) d1[i] = s1[i];
        int4* d2 = (int4*)(smc + SB_WB);
        const int4* s2 = (const int4*)g_wb;
        for (int i = tid; i < 30720 / 16; i += NT) d2[i] = s2[i];
        float* bf = (float*)(smc + SB_BI);
        if (tid < 64) bf[tid] = g_bi[tid];
        float* bm = (float*)(smc + SB_BMX);
        if (tid < 65) bm[tid] = g_bmx[tid];
    }
    __syncthreads();

    const __half* sw1 = (const __half*)(smc + SB_W1);
    const __half* swb = (const __half*)(smc + SB_WB);
    const float*  sbi = (const float*)(smc + SB_BI);
    const float*  sbm = (const float*)(smc + SB_BMX);

    const int wid  = tid >> 5;
    const int lane = tid & 31;
    const int gq   = lane >> 2;
    const int t4   = lane & 3;
    const int is64 = g_edges_is_i64;
    const long long* e64 = (const long long*)edges_raw;
    const int*       e32 = (const int*)edges_raw;
    const float bma = sbm[64];

    const char* eB = (const char*)edge_fts;
    const char* nH = (const char*)g_nodeh;
    const int ntiles  = (n_edges + 15) >> 4;
    const int wstride = gridDim.x * 8;

#define LOADIDX(dh, dt, tw) do { \
        size_t ep = (size_t)min(((tw) << 4) + lane, n_edges - 1); \
        if (is64) { dh = (int)e64[ep]; dt = (int)e64[ep + (size_t)n_edges]; } \
        else      { dh = e32[ep];      dt = e32[ep + (size_t)n_edges]; } \
    } while (0)

#define SETPTRS(PE0, PE1, OH0, OH1, OT0, OT1, HI, TI, tw) do { \
        { const int er0 = min(((tw) << 4) + gq,     n_edges - 1); \
          const int er1 = min(((tw) << 4) + 8 + gq, n_edges - 1); \
          PE0 = eB + (size_t)er0 * 256 + (size_t)(t4 * 16); \
          PE1 = eB + (size_t)er1 * 256 + (size_t)(t4 * 16); } \
        { const int h0 = __shfl_sync(0xffffffffu, HI, gq); \
          const int h1 = __shfl_sync(0xffffffffu, HI, 8 + gq); \
          const int tt0 = __shfl_sync(0xffffffffu, TI, gq); \
          const int tt1 = __shfl_sync(0xffffffffu, TI, 8 + gq); \
          OH0 = (uint32_t)h0 * 128u + (uint32_t)(t4 * 16); \
          OH1 = (uint32_t)h1 * 128u + (uint32_t)(t4 * 16); \
          OT0 = (uint32_t)tt0 * 128u + (uint32_t)(t4 * 16); \
          OT1 = (uint32_t)tt1 * 128u + (uint32_t)(t4 * 16); } \
    } while (0)

// batched weight mma for one step: wb slot -> 9 nt ; optional w1 slot -> 8 nt
#define WB_MMA(sidx, A0, A1, A2, A3) do { \
        const __half* wp = swb + ((sidx) * 32 + lane) * 40; \
        uint4 wA = *(const uint4*)wp; \
        uint4 wBv = *(const uint4*)(wp + 8); \
        uint4 wC = *(const uint4*)(wp + 16); \
        uint4 wD = *(const uint4*)(wp + 24); \
        uint2 wE = *(const uint2*)(wp + 32); \
        mma_f16(accB[0], A0, A1, A2, A3, wA.x, wA.y); \
        mma_f16(accB[1], A0, A1, A2, A3, wA.z, wA.w); \
        mma_f16(accB[2], A0, A1, A2, A3, wBv.x, wBv.y); \
        mma_f16(accB[3], A0, A1, A2, A3, wBv.z, wBv.w); \
        mma_f16(accB[4], A0, A1, A2, A3, wC.x, wC.y); \
        mma_f16(accB[5], A0, A1, A2, A3, wC.z, wC.w); \
        mma_f16(accB[6], A0, A1, A2, A3, wD.x, wD.y); \
        mma_f16(accB[7], A0, A1, A2, A3, wD.z, wD.w); \
        mma_f16(accB[8], A0, A1, A2, A3, wE.x, wE.y); \
    } while (0)

#define W1_MMA(sidx, A0, A1, A2, A3) do { \
        const __half* wp = sw1 + ((sidx) * 32 + lane) * 40; \
        uint4 wA = *(const uint4*)wp; \
        uint4 wBv = *(const uint4*)(wp + 8); \
        uint4 wC = *(const uint4*)(wp + 16); \
        uint4 wD = *(const uint4*)(wp + 24); \
        mma_f16(accE[0], A0, A1, A2, A3, wA.x, wA.y); \
        mma_f16(accE[1], A0, A1, A2, A3, wA.z, wA.w); \
        mma_f16(accE[2], A0, A1, A2, A3, wBv.x, wBv.y); \
        mma_f16(accE[3], A0, A1, A2, A3, wBv.z, wBv.w); \
        mma_f16(accE[4], A0, A1, A2, A3, wC.x, wC.y); \
        mma_f16(accE[5], A0, A1, A2, A3, wC.z, wC.w); \
        mma_f16(accE[6], A0, A1, A2, A3, wD.x, wD.y); \
        mma_f16(accE[7], A0, A1, A2, A3, wD.z, wD.w); \
    } while (0)

    int wt = blockIdx.x * 8 + wid;
    if (wt >= ntiles) return;

    // ---------------- prologue: tile-0 state ----------------
    int hidx, tidx;
    const char *pE0, *pE1;
    uint32_t oH0, oH1, oT0, oT1;
    LOADIDX(hidx, tidx, wt);
    SETPTRS(pE0, pE1, oH0, oH1, oT0, oT1, hidx, tidx, wt);
    float4 vc0 = __ldg((const float4*)pE0);
    float4 vc1 = __ldg((const float4*)pE1);
    uint4  cc0 = __ldg((const uint4*)(nH + oH0));
    uint4  cc1 = __ldg((const uint4*)(nH + oH1));

    for (; wt < ntiles; wt += wstride) {
        const int tb  = wt << 4;
        const int rem = min(16, n_edges - tb);
        const int wtn = min(wt + wstride, ntiles - 1);

        int hidxN, tidxN;
        LOADIDX(hidxN, tidxN, wtn);

        float accE[8][4], accB[9][4];
        #pragma unroll
        for (int b = 0; b < 8; ++b)
            #pragma unroll
            for (int c = 0; c < 4; ++c) accE[b][c] = 0.f;
        #pragma unroll
        for (int b = 0; b < 9; ++b)
            #pragma unroll
            for (int c = 0; c < 4; ++c) accB[b][c] = 0.f;

        // -------- edge phase: s = 0..3, both GEMMs --------
        #pragma unroll
        for (int s = 0; s < 4; ++s) {
            float4 vn0, vn1;
            if (s < 3) {
                vn0 = __ldg((const float4*)(pE0 + (s + 1) * 64));
                vn1 = __ldg((const float4*)(pE1 + (s + 1) * 64));
            }
            const uint32_t a0 = H2(vc0.x, vc0.y), a1 = H2(vc1.x, vc1.y);
            const uint32_t a2 = H2(vc0.z, vc0.w), a3 = H2(vc1.z, vc1.w);
            WB_MMA(s, a0, a1, a2, a3);
            W1_MMA(s, a0, a1, a2, a3);
            if (s < 3) { vc0 = vn0; vc1 = vn1; }
        }

        // pack e (+b_init) to fp16 — frees registers for cross-tile prefetch
        uint32_t eh[2][8];
        #pragma unroll
        for (int hf = 0; hf < 2; ++hf) {
            const int h2 = hf * 2;
            #pragma unroll
            for (int J = 0; J < 4; ++J) {
                float4 bi4 = *(const float4*)&sbi[J * 16 + t4 * 4];
                eh[hf][J * 2]     = H2(accE[2 * J][h2] + bi4.x,     accE[2 * J][h2 + 1] + bi4.y);
                eh[hf][J * 2 + 1] = H2(accE[2 * J + 1][h2] + bi4.z, accE[2 * J + 1][h2 + 1] + bi4.w);
            }
        }

        // -------- node phase: 4 step-pairs --------
        #pragma unroll
        for (int pj = 0; pj < 4; ++pj) {
            uint4 nn0, nn1;
            if (pj < 3) {
                const int np = pj + 1;
                const uint32_t b0 = (np >> 1) ? oT0 : oH0;
                const uint32_t b1 = (np >> 1) ? oT1 : oH1;
                nn0 = __ldg((const uint4*)(nH + b0 + (np & 1) * 64));
                nn1 = __ldg((const uint4*)(nH + b1 + (np & 1) * 64));
            }
            WB_MMA(4 + 2 * pj, cc0.x, cc1.x, cc0.y, cc1.y);
            WB_MMA(5 + 2 * pj, cc0.z, cc1.z, cc0.w, cc1.w);
            if (pj < 3) { cc0 = nn0; cc1 = nn1; }
        }

        // -------- prefetch next tile across the epilogue --------
        const char *pE0n, *pE1n;
        uint32_t oH0n, oH1n, oT0n, oT1n;
        SETPTRS(pE0n, pE1n, oH0n, oH1n, oT0n, oT1n, hidxN, tidxN, wtn);
        float4 vc0n = __ldg((const float4*)pE0n);
        float4 vc1n = __ldg((const float4*)pE1n);
        uint4  cc0n = __ldg((const uint4*)(nH + oH0n));
        uint4  cc1n = __ldg((const uint4*)(nH + oH1n));

        // ---------------- epilogue (registers only) ----------------
        #pragma unroll
        for (int hf = 0; hf < 2; ++hf) {
            const int h2  = hf * 2;
            const int row = hf * 8 + gq;

            float p[16], s1 = 0.f, s2 = 0.f;
            #pragma unroll
            for (int J = 0; J < 4; ++J) {
                float4 bm4 = *(const float4*)&sbm[J * 16 + t4 * 4];
                float pre[4] = { accB[2 * J][h2]     + bm4.x,
                                 accB[2 * J][h2 + 1] + bm4.y,
                                 accB[2 * J + 1][h2]     + bm4.z,
                                 accB[2 * J + 1][h2 + 1] + bm4.w };
                #pragma unroll
                for (int c = 0; c < 4; ++c) {
                    float th = tanhap(pre[c]);
                    p[J * 4 + c] = th;
                    s1 += th; s2 += th * th;
                }
            }
            s1 += __shfl_xor_sync(0xffffffffu, s1, 1);
            s1 += __shfl_xor_sync(0xffffffffu, s1, 2);
            s2 += __shfl_xor_sync(0xffffffffu, s2, 1);
            s2 += __shfl_xor_sync(0xffffffffu, s2, 2);
            float ap = accB[8][h2] + bma;
            ap = __shfl_sync(0xffffffffu, ap, lane & ~3);
            const float alpha = __fdividef(1.f, 1.f + __expf(-ap));
            const float mean  = s1 * (1.f / 64.f);
            const float var   = s2 * (1.f / 64.f) - mean * mean;
            const float rstd  = rsqrtf(var + LN_EPS) * alpha;

            float y[16], u1 = 0.f, u2 = 0.f;
            #pragma unroll
            for (int J = 0; J < 4; ++J) {
                float2 e01 = __half22float2(*(__half2*)&eh[hf][J * 2]);
                float2 e23 = __half22float2(*(__half2*)&eh[hf][J * 2 + 1]);
                float y0 = e01.x + (p[J * 4 + 0] - mean) * rstd;
                float y1 = e01.y + (p[J * 4 + 1] - mean) * rstd;
                float y2 = e23.x + (p[J * 4 + 2] - mean) * rstd;
                float y3 = e23.y + (p[J * 4 + 3] - mean) * rstd;
                y[J * 4 + 0] = y0; y[J * 4 + 1] = y1; y[J * 4 + 2] = y2; y[J * 4 + 3] = y3;
                u1 += y0 + y1 + y2 + y3;
                u2 += y0 * y0 + y1 * y1 + y2 * y2 + y3 * y3;
            }
            u1 += __shfl_xor_sync(0xffffffffu, u1, 1);
            u1 += __shfl_xor_sync(0xffffffffu, u1, 2);
            u2 += __shfl_xor_sync(0xffffffffu, u2, 1);
            u2 += __shfl_xor_sync(0xffffffffu, u2, 2);
            const float m2  = u1 * (1.f / 64.f);
            const float v2  = u2 * (1.f / 64.f) - m2 * m2;
            const float rs2 = rsqrtf(v2 + LN_EPS);

            if (row < rem) {
                float* op = out + (size_t)(tb + row) * 64;
                #pragma unroll
                for (int J = 0; J < 4; ++J) {
                    float4 o;
                    o.x = (y[J * 4 + 0] - m2) * rs2;
                    o.y = (y[J * 4 + 1] - m2) * rs2;
                    o.z = (y[J * 4 + 2] - m2) * rs2;
                    o.w = (y[J * 4 + 3] - m2) * rs2;
                    __stcs((float4*)(op + J * 16 + t4 * 4), o);
                }
            }
        }

        pE0 = pE0n; pE1 = pE1n;
        oH0 = oH0n; oH1 = oH1n; oT0 = oT0n; oT1 = oT1n;
        vc0 = vc0n; vc1 = vc1n; cc0 = cc0n; cc1 = cc1n;
    }
#undef LOADIDX
#undef SETPTRS
#undef WB_MMA
#undef W1_MMA
}

extern "C" void kernel_launch(void* const* d_in, const int* in_sizes, int n_in,
                              void* d_out, int out_size)
{
    const float* node_fts = (const float*)d_in[0];
    const float* edge_fts = (const float*)d_in[1];
    const void*  edges    = d_in[2];
    const float* W_init   = (const float*)d_in[3];
    const float* b_init   = (const float*)d_in[4];
    const float* W_mlp    = (const float*)d_in[5];
    const float* b_mlp    = (const float*)d_in[6];
    const float* W_alpha  = (const float*)d_in[7];
    const float* b_alpha  = (const float*)d_in[8];
    float*       out      = (float*)d_out;

    const int n_edges = in_sizes[1] / 64;
    const int n4      = in_sizes[0] / 4;
    const int ntiles  = (n_edges + 15) / 16;

    int nsm = 148;
    cudaDeviceGetAttribute(&nsm, cudaDevAttrMultiProcessorCount, 0);
    int need = (ntiles + 7) / 8;
    int maxg = 2 * nsm;
    int grid = need < maxg ? need : maxg;

    const int prep_threads = n4 + 64 * 64 + 72 * 192 + 64 + 65;

    cudaFuncSetAttribute(edge_update_v15,
                         cudaFuncAttributeMaxDynamicSharedMemorySize, SMEM_BYTES);
    prep_all<<<(prep_threads + 255) / 256, 256>>>(node_fts, n4, W_init, b_init,
                                                  W_mlp, b_mlp, W_alpha, b_alpha,
                                                  (const long long*)edges);
    edge_update_v15<<<grid, NT, SMEM_BYTES>>>(edge_fts, edges, out, n_edges);
}